// round 4
// baseline (speedup 1.0000x reference)
#include <cuda_runtime.h>

// Problem dims
#define NB 8
#define DD 32   // d1=d2=d3
#define NC 32   // in_features
#define NO 32   // out_features
// positions = NB*DD*DD*DD = 262144

typedef unsigned long long ull;

// ---------------- scratch (device globals; no allocation allowed) ----------------
__device__ float g_m1[NB*DD*DD*NC];   // [b][j][k][c]  sum over i
__device__ float g_m2[NB*DD*DD*NC];   // [b][i][k][c]  sum over j
__device__ float g_m3[NB*DD*DD*NC];   // [b][i][j][c]  sum over k
__device__ float g_pij[NB*DD*NO];     // [b][k][o]
__device__ float g_pik[NB*DD*NO];     // [b][j][o]
__device__ float g_pjk[NB*DD*NO];     // [b][i][o]
__device__ float g_pall[NB*NO];       // [b][o]  (includes bias)
__device__ float g_PA[NB*DD*DD*NO];   // [b][j][k][o]
__device__ float g_PB[NB*DD*DD*NO];   // [b][i][k][o]
__device__ float g_PC[NB*DD*DD*NO];   // [b][i][j][o]

// ---------------- packed f32x2 helpers ----------------
__device__ __forceinline__ ull pack_dup(float v) {
    ull r;
    asm("mov.b64 %0, {%1, %1};" : "=l"(r) : "r"(__float_as_uint(v)));
    return r;
}
__device__ __forceinline__ ull pack2(float a, float b) {
    ull r;
    asm("mov.b64 %0, {%1, %2};" : "=l"(r) : "r"(__float_as_uint(a)), "r"(__float_as_uint(b)));
    return r;
}
__device__ __forceinline__ float2 unpack2(ull v) {
    float2 r;
    asm("mov.b64 {%0, %1}, %2;" : "=f"(r.x), "=f"(r.y) : "l"(v));
    return r;
}
#define FMA2(acc, a, b) asm("fma.rn.f32x2 %0, %1, %2, %0;" : "+l"(acc) : "l"(a), "l"(b))

// ---------------- K1: axis sums m1,m2,m3 (grid 768) ----------------
__global__ __launch_bounds__(256) void k_means(const float* __restrict__ x) {
    int sel = blockIdx.x >> 8;        // 0:m1, 1:m2, 2:m3
    int blk = blockIdx.x & 255;
    int b = blk >> 5, d = blk & 31;
    int t = threadIdx.x;
    const float4* x4 = (const float4*)x;

    if (sel == 0) {
        float4 acc = make_float4(0.f, 0.f, 0.f, 0.f);
        #pragma unroll 8
        for (int i = 0; i < DD; i++) {
            float4 v = x4[((b * DD + i) * DD + d) * 256 + t];
            acc.x += v.x; acc.y += v.y; acc.z += v.z; acc.w += v.w;
        }
        ((float4*)g_m1)[(b * DD + d) * 256 + t] = acc;
    } else if (sel == 1) {
        float4 acc = make_float4(0.f, 0.f, 0.f, 0.f);
        #pragma unroll 8
        for (int j = 0; j < DD; j++) {
            float4 v = x4[((b * DD + d) * DD + j) * 256 + t];
            acc.x += v.x; acc.y += v.y; acc.z += v.z; acc.w += v.w;
        }
        ((float4*)g_m2)[(b * DD + d) * 256 + t] = acc;
    } else {
        int j = t >> 3, c4 = t & 7;
        float4 acc = make_float4(0.f, 0.f, 0.f, 0.f);
        #pragma unroll 8
        for (int k = 0; k < DD; k++) {
            float4 v = x4[((b * DD + d) * DD + j) * 256 + k * 8 + c4];
            acc.x += v.x; acc.y += v.y; acc.z += v.z; acc.w += v.w;
        }
        ((float4*)g_m3)[(b * DD + d) * 256 + j * 8 + c4] = acc;
    }
}

// ---------------- K2: fused 2/3-axis pools + small projections (grid 776) ----------------
__global__ __launch_bounds__(128) void k_small(const float* __restrict__ W,
                                               const float* __restrict__ bias) {
    __shared__ float part[128];
    __shared__ float mrow[NC];
    int gid = blockIdx.x;
    int t = threadIdx.x;
    int c = t & 31, q = t >> 5;     // q in 0..3

    float s = 0.f;
    const float* w;
    float scale;
    float* dst;
    bool addb = false;

    if (gid < 256) {
        int b = gid >> 5, k = gid & 31;
        #pragma unroll
        for (int j = q; j < DD; j += 4) s += g_m1[((b * DD + j) * DD + k) * NC + c];
        w = W + 128; scale = 1.0f / 1024.0f; dst = g_pij + gid * NO;
    } else if (gid < 512) {
        int g = gid - 256;
        int b = g >> 5, j = g & 31;
        #pragma unroll
        for (int k = q; k < DD; k += 4) s += g_m1[((b * DD + j) * DD + k) * NC + c];
        w = W + 160; scale = 1.0f / 1024.0f; dst = g_pik + g * NO;
    } else if (gid < 768) {
        int g = gid - 512;
        int b = g >> 5, i = g & 31;
        #pragma unroll
        for (int k = q; k < DD; k += 4) s += g_m2[((b * DD + i) * DD + k) * NC + c];
        w = W + 192; scale = 1.0f / 1024.0f; dst = g_pjk + g * NO;
    } else {
        int b = gid - 768;
        for (int jk = q; jk < DD * DD; jk += 4) s += g_m1[(b * DD * DD + jk) * NC + c];
        w = W + 224; scale = 1.0f / 32768.0f; dst = g_pall + b * NO; addb = true;
    }
    part[t] = s;
    __syncthreads();
    if (t < 32) {
        mrow[t] = part[t] + part[t + 32] + part[t + 64] + part[t + 96];
    }
    __syncthreads();
    if (t < 32) {
        float acc = 0.f;
        #pragma unroll
        for (int cc = 0; cc < NC; cc++) acc += mrow[cc] * w[t * 256 + cc];
        acc *= scale;
        if (addb) acc += bias[t];
        dst[t] = acc;
    }
}

// ---------------- K3: PA/PB/PC projections of m1/m2/m3 (grid 192) ----------------
__global__ __launch_bounds__(256) void k_bigproj(const float* __restrict__ W) {
    int sel = blockIdx.x >> 6;       // 64 blocks per source (8192 rows each)
    __shared__ float Ws[NC * NO];    // [c][o], pre-scaled by 1/32
    {
        int idx = threadIdx.x;
        #pragma unroll
        for (int qq = 0; qq < 4; qq++, idx += 256) {
            int c = idx >> 5, o = idx & 31;
            Ws[idx] = W[o * 256 + (1 + sel) * 32 + c] * (1.0f / 32.0f);
        }
    }
    __syncthreads();

    int p = (blockIdx.x & 63) * 128 + (threadIdx.x >> 1);   // row within source
    int half = threadIdx.x & 1;                              // outputs [half*16, half*16+16)
    const float* src = (sel == 0) ? g_m1 : (sel == 1) ? g_m2 : g_m3;
    const float4* xr = (const float4*)(src + p * NC);

    ull acc[8];
    #pragma unroll
    for (int o2 = 0; o2 < 8; o2++) acc[o2] = 0ull;

    #pragma unroll
    for (int c4 = 0; c4 < 8; c4++) {
        float4 a4 = xr[c4];
        #pragma unroll
        for (int cc = 0; cc < 4; cc++) {
            ull av2 = pack_dup(((const float*)&a4)[cc]);
            const ull* wrow = (const ull*)(Ws + (c4 * 4 + cc) * NO + half * 16);
            #pragma unroll
            for (int o2 = 0; o2 < 8; o2++) FMA2(acc[o2], av2, wrow[o2]);
        }
    }

    int b = p >> 10, d1 = (p >> 5) & 31, d2 = p & 31;
    float add[16];
    #pragma unroll
    for (int o = 0; o < 16; o++) add[o] = 0.f;
    float* dst;
    if (sel == 0) {
        dst = g_PA;
        const float* px = g_pij + (b * 32 + d2) * NO + half * 16;  // [b][k]
        const float* py = g_pik + (b * 32 + d1) * NO + half * 16;  // [b][j]
        const float* pz = g_pall + b * NO + half * 16;
        #pragma unroll
        for (int o = 0; o < 16; o++) add[o] = px[o] + py[o] + pz[o];
    } else if (sel == 1) {
        dst = g_PB;
        const float* px = g_pjk + (b * 32 + d1) * NO + half * 16;  // [b][i]
        #pragma unroll
        for (int o = 0; o < 16; o++) add[o] = px[o];
    } else {
        dst = g_PC;
    }

    float4* dv = (float4*)(dst + p * NO + half * 16);
    #pragma unroll
    for (int o4 = 0; o4 < 4; o4++) {
        float2 v0 = unpack2(acc[o4 * 2]);
        float2 v1 = unpack2(acc[o4 * 2 + 1]);
        float4 r;
        r.x = v0.x + add[o4 * 4 + 0];
        r.y = v0.y + add[o4 * 4 + 1];
        r.z = v1.x + add[o4 * 4 + 2];
        r.w = v1.y + add[o4 * 4 + 3];
        dv[o4] = r;
    }
}

// ---------------- K4: main projection, dup'd-x register-tiled (grid 2048 x 128) ----------------
// Block: 128 rows x 32 outputs. Thread (pg,og): rows pg*4..pg*4+3, outputs og*8..+7.
// x stored in smem PRE-DUPLICATED as f32x2 pairs, layout [pg][c][r], pg-stride
// PGS=134 ull so the 8 pg addresses of a warp hit 8 distinct 16B bank-quads
// (67*pg mod 8 = 3*pg mod 8 -> all distinct). Mainloop per c: 2 LDS.128 (x, 4
// rows) + 2 LDS.128 (W, broadcast) + 16 FMA2 -> 80% of issue is FMA2.
#define PGS 134
__global__ __launch_bounds__(128) void k_main(const float* __restrict__ x,
                                              const float* __restrict__ W,
                                              float* __restrict__ out) {
    __shared__ ull x_s[32 * PGS];     // [pg][c][r] dup'd pairs, padded
    __shared__ ull Wu[NC * 16];       // [c][o2] : (W[2*o2][c], W[2*o2+1][c])

    int tid = threadIdx.x;
    int p0 = blockIdx.x * 128;
    int b = p0 >> 15, i = (p0 >> 10) & 31, j0 = (p0 >> 5) & 31;  // block: 4 j values, all k

    // ---- stage W ----
    #pragma unroll
    for (int idx = tid; idx < 512; idx += 128) {
        int c = idx >> 4, o2 = idx & 15;
        Wu[c * 16 + o2] = pack2(W[(2 * o2) * 256 + c], W[(2 * o2 + 1) * 256 + c]);
    }
    // ---- stage x: 1024 float4 -> dup'd ulls ----
    {
        const float4* xg = (const float4*)(x + (size_t)p0 * 32);
        #pragma unroll
        for (int pass = 0; pass < 8; pass++) {
            int idx = pass * 128 + tid;
            int row = idx >> 3, c4 = idx & 7;
            float4 v = xg[idx];
            ull* d = x_s + (row >> 2) * PGS + (row & 3);
            d[(c4 * 4 + 0) * 4] = pack_dup(v.x);
            d[(c4 * 4 + 1) * 4] = pack_dup(v.y);
            d[(c4 * 4 + 2) * 4] = pack_dup(v.z);
            d[(c4 * 4 + 3) * 4] = pack_dup(v.w);
        }
    }
    __syncthreads();

    int pg = tid >> 2;          // 0..31 : row group (4 rows)
    int og = tid & 3;           // 0..3  : output group (8 outputs)

    const ull* xr = x_s + pg * PGS;
    const ull* wp = Wu + og * 4;

    ull acc[4][4];
    #pragma unroll
    for (int r = 0; r < 4; r++)
        #pragma unroll
        for (int w = 0; w < 4; w++) acc[r][w] = 0ull;

    #pragma unroll 8
    for (int c = 0; c < NC; c++) {
        ulonglong2 xa = *(const ulonglong2*)(xr + c * 4);       // rows 0,1 dup'd
        ulonglong2 xb = *(const ulonglong2*)(xr + c * 4 + 2);   // rows 2,3 dup'd
        ulonglong2 wa = *(const ulonglong2*)(wp + c * 16);      // outs 0-3
        ulonglong2 wb = *(const ulonglong2*)(wp + c * 16 + 2);  // outs 4-7
        FMA2(acc[0][0], xa.x, wa.x); FMA2(acc[0][1], xa.x, wa.y);
        FMA2(acc[0][2], xa.x, wb.x); FMA2(acc[0][3], xa.x, wb.y);
        FMA2(acc[1][0], xa.y, wa.x); FMA2(acc[1][1], xa.y, wa.y);
        FMA2(acc[1][2], xa.y, wb.x); FMA2(acc[1][3], xa.y, wb.y);
        FMA2(acc[2][0], xb.x, wa.x); FMA2(acc[2][1], xb.x, wa.y);
        FMA2(acc[2][2], xb.x, wb.x); FMA2(acc[2][3], xb.x, wb.y);
        FMA2(acc[3][0], xb.y, wa.x); FMA2(acc[3][1], xb.y, wa.y);
        FMA2(acc[3][2], xb.y, wb.x); FMA2(acc[3][3], xb.y, wb.y);
    }

    // ---- epilogue: + PA[b][j][k] + PB[b][i][k] + PC[b][i][j], store out ----
    #pragma unroll
    for (int r = 0; r < 4; r++) {
        int rl = pg * 4 + r;                 // 0..127
        int k = rl & 31, jj = rl >> 5;       // jj 0..3
        const float4* pa = (const float4*)(g_PA + ((((b * 32 + j0 + jj) * 32 + k) * 32) + og * 8));
        const float4* pb = (const float4*)(g_PB + ((((b * 32 + i) * 32 + k) * 32) + og * 8));
        const float4* pc = (const float4*)(g_PC + ((((b * 32 + i) * 32 + j0 + jj) * 32) + og * 8));
        float4 a0 = pa[0], a1 = pa[1];
        float4 b0 = pb[0], b1 = pb[1];
        float4 c0 = pc[0], c1 = pc[1];
        float2 v0 = unpack2(acc[r][0]);
        float2 v1 = unpack2(acc[r][1]);
        float2 v2 = unpack2(acc[r][2]);
        float2 v3 = unpack2(acc[r][3]);
        float4 r0, r1;
        r0.x = v0.x + a0.x + b0.x + c0.x;
        r0.y = v0.y + a0.y + b0.y + c0.y;
        r0.z = v1.x + a0.z + b0.z + c0.z;
        r0.w = v1.y + a0.w + b0.w + c0.w;
        r1.x = v2.x + a1.x + b1.x + c1.x;
        r1.y = v2.y + a1.y + b1.y + c1.y;
        r1.z = v3.x + a1.z + b1.z + c1.z;
        r1.w = v3.y + a1.w + b1.w + c1.w;
        float4* dst = (float4*)(out + (size_t)(p0 + rl) * 32 + og * 8);
        dst[0] = r0;
        dst[1] = r1;
    }
}

// ---------------- launch ----------------
extern "C" void kernel_launch(void* const* d_in, const int* in_sizes, int n_in,
                              void* d_out, int out_size) {
    const float* x    = (const float*)d_in[0];
    const float* W    = (const float*)d_in[1];
    const float* bias = (const float*)d_in[2];
    float* out = (float*)d_out;

    k_means<<<768, 256>>>(x);
    k_small<<<776, 128>>>(W, bias);
    k_bigproj<<<192, 256>>>(W);
    k_main<<<2048, 128>>>(x, W, out);
}

// round 5
// speedup vs baseline: 1.7961x; 1.7961x over previous
#include <cuda_runtime.h>

// Problem dims
#define NB 8
#define DD 32   // d1=d2=d3
#define NC 32   // in_features
#define NO 32   // out_features
// positions = NB*DD*DD*DD = 262144

typedef unsigned long long ull;

// ---------------- scratch (device globals; no allocation allowed) ----------------
__device__ float g_m1[NB*DD*DD*NC];   // [b][j][k][c]  sum over i
__device__ float g_m2[NB*DD*DD*NC];   // [b][i][k][c]  sum over j
__device__ float g_m3[NB*DD*DD*NC];   // [b][i][j][c]  sum over k
__device__ float g_pij[NB*DD*NO];     // [b][k][o]
__device__ float g_pik[NB*DD*NO];     // [b][j][o]
__device__ float g_pjk[NB*DD*NO];     // [b][i][o]
__device__ float g_pall[NB*NO];       // [b][o]  (includes bias)
__device__ float g_PA[NB*DD*DD*NO];   // [b][j][k][o]
__device__ float g_PB[NB*DD*DD*NO];   // [b][i][k][o]
__device__ float g_PC[NB*DD*DD*NO];   // [b][i][j][o]

// ---------------- packed f32x2 helpers ----------------
__device__ __forceinline__ ull pack_dup(float v) {
    ull r;
    asm("mov.b64 %0, {%1, %1};" : "=l"(r) : "r"(__float_as_uint(v)));
    return r;
}
__device__ __forceinline__ float2 unpack2(ull v) {
    float2 r;
    asm("mov.b64 {%0, %1}, %2;" : "=f"(r.x), "=f"(r.y) : "l"(v));
    return r;
}
#define FMA2(acc, a, b) asm("fma.rn.f32x2 %0, %1, %2, %0;" : "+l"(acc) : "l"(a), "l"(b))

// ---------------- K1: axis sums m1,m2,m3 (grid 768) ----------------
__global__ __launch_bounds__(256) void k_means(const float* __restrict__ x) {
    int sel = blockIdx.x >> 8;        // 0:m1, 1:m2, 2:m3
    int blk = blockIdx.x & 255;
    int b = blk >> 5, d = blk & 31;
    int t = threadIdx.x;
    const float4* x4 = (const float4*)x;

    if (sel == 0) {
        float4 acc = make_float4(0.f, 0.f, 0.f, 0.f);
        #pragma unroll 8
        for (int i = 0; i < DD; i++) {
            float4 v = x4[((b * DD + i) * DD + d) * 256 + t];
            acc.x += v.x; acc.y += v.y; acc.z += v.z; acc.w += v.w;
        }
        ((float4*)g_m1)[(b * DD + d) * 256 + t] = acc;
    } else if (sel == 1) {
        float4 acc = make_float4(0.f, 0.f, 0.f, 0.f);
        #pragma unroll 8
        for (int j = 0; j < DD; j++) {
            float4 v = x4[((b * DD + d) * DD + j) * 256 + t];
            acc.x += v.x; acc.y += v.y; acc.z += v.z; acc.w += v.w;
        }
        ((float4*)g_m2)[(b * DD + d) * 256 + t] = acc;
    } else {
        int j = t >> 3, c4 = t & 7;
        float4 acc = make_float4(0.f, 0.f, 0.f, 0.f);
        #pragma unroll 8
        for (int k = 0; k < DD; k++) {
            float4 v = x4[((b * DD + d) * DD + j) * 256 + k * 8 + c4];
            acc.x += v.x; acc.y += v.y; acc.z += v.z; acc.w += v.w;
        }
        ((float4*)g_m3)[(b * DD + d) * 256 + j * 8 + c4] = acc;
    }
}

// ---------------- K2: fused 2/3-axis pools + small projections (grid 776) ----------------
__global__ __launch_bounds__(128) void k_small(const float* __restrict__ W,
                                               const float* __restrict__ bias) {
    __shared__ float part[128];
    __shared__ float mrow[NC];
    int gid = blockIdx.x;
    int t = threadIdx.x;
    int c = t & 31, q = t >> 5;     // q in 0..3

    float s = 0.f;
    const float* w;
    float scale;
    float* dst;
    bool addb = false;

    if (gid < 256) {
        int b = gid >> 5, k = gid & 31;
        #pragma unroll
        for (int j = q; j < DD; j += 4) s += g_m1[((b * DD + j) * DD + k) * NC + c];
        w = W + 128; scale = 1.0f / 1024.0f; dst = g_pij + gid * NO;
    } else if (gid < 512) {
        int g = gid - 256;
        int b = g >> 5, j = g & 31;
        #pragma unroll
        for (int k = q; k < DD; k += 4) s += g_m1[((b * DD + j) * DD + k) * NC + c];
        w = W + 160; scale = 1.0f / 1024.0f; dst = g_pik + g * NO;
    } else if (gid < 768) {
        int g = gid - 512;
        int b = g >> 5, i = g & 31;
        #pragma unroll
        for (int k = q; k < DD; k += 4) s += g_m2[((b * DD + i) * DD + k) * NC + c];
        w = W + 192; scale = 1.0f / 1024.0f; dst = g_pjk + g * NO;
    } else {
        int b = gid - 768;
        for (int jk = q; jk < DD * DD; jk += 4) s += g_m1[(b * DD * DD + jk) * NC + c];
        w = W + 224; scale = 1.0f / 32768.0f; dst = g_pall + b * NO; addb = true;
    }
    part[t] = s;
    __syncthreads();
    if (t < 32) {
        mrow[t] = part[t] + part[t + 32] + part[t + 64] + part[t + 96];
    }
    __syncthreads();
    if (t < 32) {
        float acc = 0.f;
        #pragma unroll
        for (int cc = 0; cc < NC; cc++) acc += mrow[cc] * w[t * 256 + cc];
        acc *= scale;
        if (addb) acc += bias[t];
        dst[t] = acc;
    }
}

// ---------------- K3: PA/PB/PC projections of m1/m2/m3 (grid 192) ----------------
__global__ __launch_bounds__(256) void k_bigproj(const float* __restrict__ W) {
    int sel = blockIdx.x >> 6;       // 64 blocks per source (8192 rows each)
    __shared__ float Ws[NC * NO];    // [c][o], pre-scaled by 1/32
    {
        int idx = threadIdx.x;
        #pragma unroll
        for (int qq = 0; qq < 4; qq++, idx += 256) {
            int c = idx >> 5, o = idx & 31;
            Ws[idx] = W[o * 256 + (1 + sel) * 32 + c] * (1.0f / 32.0f);
        }
    }
    __syncthreads();

    int p = (blockIdx.x & 63) * 128 + (threadIdx.x >> 1);   // row within source
    int half = threadIdx.x & 1;                              // outputs [half*16, half*16+16)
    const float* src = (sel == 0) ? g_m1 : (sel == 1) ? g_m2 : g_m3;
    const float4* xr = (const float4*)(src + p * NC);

    ull acc[8];
    #pragma unroll
    for (int o2 = 0; o2 < 8; o2++) acc[o2] = 0ull;

    #pragma unroll
    for (int c4 = 0; c4 < 8; c4++) {
        float4 a4 = xr[c4];
        #pragma unroll
        for (int cc = 0; cc < 4; cc++) {
            ull av2 = pack_dup(((const float*)&a4)[cc]);
            const ull* wrow = (const ull*)(Ws + (c4 * 4 + cc) * NO + half * 16);
            #pragma unroll
            for (int o2 = 0; o2 < 8; o2++) FMA2(acc[o2], av2, wrow[o2]);
        }
    }

    int b = p >> 10, d1 = (p >> 5) & 31, d2 = p & 31;
    float add[16];
    #pragma unroll
    for (int o = 0; o < 16; o++) add[o] = 0.f;
    float* dst;
    if (sel == 0) {
        dst = g_PA;
        const float* px = g_pij + (b * 32 + d2) * NO + half * 16;  // [b][k]
        const float* py = g_pik + (b * 32 + d1) * NO + half * 16;  // [b][j]
        const float* pz = g_pall + b * NO + half * 16;
        #pragma unroll
        for (int o = 0; o < 16; o++) add[o] = px[o] + py[o] + pz[o];
    } else if (sel == 1) {
        dst = g_PB;
        const float* px = g_pjk + (b * 32 + d1) * NO + half * 16;  // [b][i]
        #pragma unroll
        for (int o = 0; o < 16; o++) add[o] = px[o];
    } else {
        dst = g_PC;
    }

    float4* dv = (float4*)(dst + p * NO + half * 16);
    #pragma unroll
    for (int o4 = 0; o4 < 4; o4++) {
        float2 v0 = unpack2(acc[o4 * 2]);
        float2 v1 = unpack2(acc[o4 * 2 + 1]);
        float4 r;
        r.x = v0.x + add[o4 * 4 + 0];
        r.y = v0.y + add[o4 * 4 + 1];
        r.z = v1.x + add[o4 * 4 + 2];
        r.w = v1.y + add[o4 * 4 + 3];
        dv[o4] = r;
    }
}

// ---------------- K4: main projection, row-paired accumulators (grid 1024 x 256) ----------------
// Block = 256 rows (fixed b,i; 8 j values x 32 k). Thread (pg,og): rows pg*4..+3,
// outputs og*8..+7. x transposed in smem x_t[c][row] (c-stride 268 floats): one
// LDS.128 per c gives 4 rows = 2 natural f32x2 row-pairs (no pack MOVs).
// W duplicated per og-section Wd[og][c][8] (section stride 258 ull -> quad
// stride 129 == 1 mod 8 -> og 0..3 hit distinct bank-quads, conflict-free).
// Mainloop per c: 5 LDS.128 + 16 FMA2.
#define XTS 268
#define WSEC 258
__global__ __launch_bounds__(256) void k_main(const float* __restrict__ x,
                                              const float* __restrict__ W,
                                              float* __restrict__ out) {
    __shared__ __align__(16) float x_t[NC * XTS];   // [c][row], 34304 B
    __shared__ __align__(16) ull   Wd[4 * WSEC];    // [og][c][8] dup'd, 8256 B

    int tid = threadIdx.x;
    int p0 = blockIdx.x * 256;
    int b = p0 >> 15, i = (p0 >> 10) & 31, j0 = (p0 >> 5) & 31;  // 8 j values

    // ---- stage W dup'd: Wd[og*WSEC + c*8 + oo] = dup(W[(og*8+oo)*256 + c]) ----
    #pragma unroll
    for (int idx = tid; idx < 1024; idx += 256) {
        int og_ = idx >> 8, rem = idx & 255;
        int c = rem >> 3, oo = rem & 7;
        Wd[og_ * WSEC + c * 8 + oo] = pack_dup(W[(og_ * 8 + oo) * 256 + c]);
    }
    // ---- stage x transposed: x_t[c][row] ----
    {
        int c = tid & 31, rg8 = tid >> 5;       // rg8 in 0..7 -> rows rg8*32..+31
        const float* xb = x + (size_t)p0 * 32 + c;
        #pragma unroll
        for (int qq = 0; qq < 8; qq++) {
            int row4 = rg8 * 32 + qq * 4;
            float4 v;
            v.x = xb[(row4 + 0) * 32];
            v.y = xb[(row4 + 1) * 32];
            v.z = xb[(row4 + 2) * 32];
            v.w = xb[(row4 + 3) * 32];
            *(float4*)(x_t + c * XTS + row4) = v;   // STS.128, 4-phase minimum
        }
    }
    __syncthreads();

    int pg = tid >> 2;          // 0..63 : row group (4 rows)
    int og = tid & 3;           // 0..3  : output group (8 outputs)

    const float* xr = x_t + pg * 4;
    const ull*   wp = Wd + og * WSEC;

    ull accA[8], accB[8];       // accA: rows (+0,+1) lanes; accB: rows (+2,+3)
    #pragma unroll
    for (int o = 0; o < 8; o++) { accA[o] = 0ull; accB[o] = 0ull; }

    #pragma unroll
    for (int c = 0; c < NC; c++) {
        ulonglong2 u = *(const ulonglong2*)(xr + c * XTS);          // rows 0..3 at column c
        ulonglong2 w01 = *(const ulonglong2*)(wp + c * 8);
        ulonglong2 w23 = *(const ulonglong2*)(wp + c * 8 + 2);
        ulonglong2 w45 = *(const ulonglong2*)(wp + c * 8 + 4);
        ulonglong2 w67 = *(const ulonglong2*)(wp + c * 8 + 6);
        FMA2(accA[0], u.x, w01.x); FMA2(accA[1], u.x, w01.y);
        FMA2(accA[2], u.x, w23.x); FMA2(accA[3], u.x, w23.y);
        FMA2(accA[4], u.x, w45.x); FMA2(accA[5], u.x, w45.y);
        FMA2(accA[6], u.x, w67.x); FMA2(accA[7], u.x, w67.y);
        FMA2(accB[0], u.y, w01.x); FMA2(accB[1], u.y, w01.y);
        FMA2(accB[2], u.y, w23.x); FMA2(accB[3], u.y, w23.y);
        FMA2(accB[4], u.y, w45.x); FMA2(accB[5], u.y, w45.y);
        FMA2(accB[6], u.y, w67.x); FMA2(accB[7], u.y, w67.y);
    }

    // unpack: fA[oo] = (row+0, row+1), fB[oo] = (row+2, row+3)
    float2 fA[8], fB[8];
    #pragma unroll
    for (int o = 0; o < 8; o++) { fA[o] = unpack2(accA[o]); fB[o] = unpack2(accB[o]); }

    // ---- epilogue: + PA[b][j][k] + PB[b][i][k] + PC[b][i][j], store out ----
    #pragma unroll
    for (int rr = 0; rr < 4; rr++) {
        int rl = pg * 4 + rr;               // 0..255
        int k = rl & 31, jj = rl >> 5;
        const float4* pa = (const float4*)(g_PA + ((((b * 32 + j0 + jj) * 32 + k) * 32) + og * 8));
        const float4* pb = (const float4*)(g_PB + ((((b * 32 + i) * 32 + k) * 32) + og * 8));
        const float4* pc = (const float4*)(g_PC + ((((b * 32 + i) * 32 + j0 + jj) * 32) + og * 8));
        float4 a0 = pa[0], a1 = pa[1];
        float4 b0 = pb[0], b1 = pb[1];
        float4 c0 = pc[0], c1 = pc[1];
        float v0, v1, v2, v3, v4, v5, v6, v7;
        if (rr == 0) { v0=fA[0].x; v1=fA[1].x; v2=fA[2].x; v3=fA[3].x; v4=fA[4].x; v5=fA[5].x; v6=fA[6].x; v7=fA[7].x; }
        else if (rr == 1) { v0=fA[0].y; v1=fA[1].y; v2=fA[2].y; v3=fA[3].y; v4=fA[4].y; v5=fA[5].y; v6=fA[6].y; v7=fA[7].y; }
        else if (rr == 2) { v0=fB[0].x; v1=fB[1].x; v2=fB[2].x; v3=fB[3].x; v4=fB[4].x; v5=fB[5].x; v6=fB[6].x; v7=fB[7].x; }
        else { v0=fB[0].y; v1=fB[1].y; v2=fB[2].y; v3=fB[3].y; v4=fB[4].y; v5=fB[5].y; v6=fB[6].y; v7=fB[7].y; }
        float4 r0, r1;
        r0.x = v0 + a0.x + b0.x + c0.x;
        r0.y = v1 + a0.y + b0.y + c0.y;
        r0.z = v2 + a0.z + b0.z + c0.z;
        r0.w = v3 + a0.w + b0.w + c0.w;
        r1.x = v4 + a1.x + b1.x + c1.x;
        r1.y = v5 + a1.y + b1.y + c1.y;
        r1.z = v6 + a1.z + b1.z + c1.z;
        r1.w = v7 + a1.w + b1.w + c1.w;
        float4* dst = (float4*)(out + (size_t)(p0 + rl) * 32 + og * 8);
        dst[0] = r0;
        dst[1] = r1;
    }
}

// ---------------- launch ----------------
extern "C" void kernel_launch(void* const* d_in, const int* in_sizes, int n_in,
                              void* d_out, int out_size) {
    const float* x    = (const float*)d_in[0];
    const float* W    = (const float*)d_in[1];
    const float* bias = (const float*)d_in[2];
    float* out = (float*)d_out;

    k_means<<<768, 256>>>(x);
    k_small<<<776, 128>>>(W, bias);
    k_bigproj<<<192, 256>>>(W);
    k_main<<<1024, 256>>>(x, W, out);
}